// round 14
// baseline (speedup 1.0000x reference)
#include <cuda_runtime.h>
#include <cuda_fp16.h>

// ---------------------------------------------------------------------------
// N=512, MAX_DIST=16, H=32, N_SPATIAL=64, BOND_TYPES=32.
// edge_sum[i,j,k] = sum_d T[d][edge_input[i,j,d]][k],  T[d] = edge_table @ W[d]
// R14: task-mixed main kernel. Persistent blocks can't overlap across kernels
// (smem-full SMs), so phi_spd joins the SAME work-stealing task space:
//   tasks 0..4095    : phi_edge, R12 loop verbatim (256-pair tile x k-quarter)
//   tasks 4096..4607 : phi_spd, 512-pair tile, all 32 heads, 2 pairs/thread
// phi_spd's low-ILP store work fills the edge tasks' idle issue/L1 slots.
// Prep kernel: T-precompute + index pack only.
// ---------------------------------------------------------------------------

#define NN        512
#define PAIRS     (NN * NN)          // 262144
#define MAXD      16
#define H         32
#define NSPAT     64
#define T2_ELEMS  (MAXD * 16 * 32)   // 8192 half2 = 32KB
#define SHS_ELEMS (16 * NSPAT)       // 1024 half2 = 4KB
#define SMEM_BYTES ((T2_ELEMS + SHS_ELEMS) * 4)   // 36864 -> 6 blocks/SM
#define GRID      888               // 6 blocks/SM * 148 SMs
#define N_EDGE_TASKS 4096           // 1024 tiles(256 pairs) * 4 k-quarters
#define N_SPD_TASKS  512            // 512-pair tiles, all 32 heads
#define N_TASKS   (N_EDGE_TASKS + N_SPD_TASKS)   // 4608

__device__ __half2   g_T2[T2_ELEMS];   // [d][k2][e]
__device__ uint4     g_packed[PAIRS];  // 16 indices, pre-scaled x4, one byte each
__device__ unsigned  g_task_counter;

// Blocks 0..15: T[d]. Blocks 16..527: index pack (2 pairs/thread).
__global__ __launch_bounds__(256)
void prep_kernel(const float* __restrict__ edge_table,
                 const float* __restrict__ W,
                 const int* __restrict__ edge_input) {
    __shared__ float shBuf[2048];
    int t = threadIdx.x;

    if (blockIdx.x < MAXD) {
        float* shE = shBuf;            // [h][e]
        float* shW = shBuf + H * H;    // [h][k]
        int d = blockIdx.x;
        for (int i = t; i < H * H; i += 256) {
            int e = i >> 5, h = i & 31;
            shE[h * H + e] = edge_table[i];
            shW[i] = W[d * (H * H) + i];
        }
        __syncthreads();
        int e = t & 31;
#pragma unroll
        for (int rep = 0; rep < 2; ++rep) {
            int k2 = (t >> 5) + 8 * rep;
            float s0 = 0.0f, s1 = 0.0f;
#pragma unroll
            for (int h = 0; h < H; ++h) {
                float ev = shE[h * H + e];          // bank = e, conflict-free
                s0 += ev * shW[h * H + 2 * k2];     // broadcast
                s1 += ev * shW[h * H + 2 * k2 + 1];
            }
            g_T2[d * 512 + k2 * 32 + e] = __floats2half2_rn(s0, s1);
        }
        return;
    }

    if (blockIdx.x == MAXD && t == 0) g_task_counter = 0u;

    int pA = ((blockIdx.x - MAXD) * 256 + t) * 2;   // 512 blocks cover PAIRS
#pragma unroll
    for (int pp = 0; pp < 2; ++pp) {
        int pair = pA + pp;
        const int4* ep = (const int4*)edge_input + pair * 4;
        int4 a = ep[0], b = ep[1], c = ep[2], e4 = ep[3];
        uint4 r;
        r.x = ((unsigned)a.x  << 2) | ((unsigned)a.y  << 10) | ((unsigned)a.z  << 18) | ((unsigned)a.w  << 26);
        r.y = ((unsigned)b.x  << 2) | ((unsigned)b.y  << 10) | ((unsigned)b.z  << 18) | ((unsigned)b.w  << 26);
        r.z = ((unsigned)c.x  << 2) | ((unsigned)c.y  << 10) | ((unsigned)c.z  << 18) | ((unsigned)c.w  << 26);
        r.w = ((unsigned)e4.x << 2) | ((unsigned)e4.y << 10) | ((unsigned)e4.z << 18) | ((unsigned)e4.w << 26);
        g_packed[pair] = r;
    }
}

__global__ __launch_bounds__(256, 6)
void bond_encoding_kernel(const int* __restrict__ spatial_pos,
                          const float* __restrict__ spd_table,
                          float* __restrict__ out) {
    extern __shared__ float sh[];
    __half2* shT = (__half2*)sh;              // [d][k2][e], 32KB
    __half2* shS = (__half2*)sh + T2_ELEMS;   // [k2][sp],   4KB
    __shared__ int mail[2];
    const int t = threadIdx.x;

    {
        const float4* src = (const float4*)g_T2;
        float4* dst = (float4*)sh;
#pragma unroll
        for (int i = t; i < T2_ELEMS / 4; i += 256)
            dst[i] = src[i];
    }
    for (int i = t; i < SHS_ELEMS; i += 256) {
        int k2 = i >> 6;
        int sp = i & 63;
        shS[i] = __floats2half2_rn(spd_table[sp * H + 2 * k2],
                                   spd_table[sp * H + 2 * k2 + 1]);
    }
    if (t == 0) mail[0] = (int)atomicAdd(&g_task_counter, 1u);
    __syncthreads();

    int task = mail[0];
    int slot = 1;
    while (task < N_TASKS) {
        if (t == 0) mail[slot] = (int)atomicAdd(&g_task_counter, 1u);

        if (task < N_EDGE_TASKS) {
            // ---------------- phi_edge task (R12 loop verbatim) ----------
            int tile = task >> 2;
            int kq   = task & 3;                  // k-quarter: 8 heads
            int pair = tile * 256 + t;

            uint4 pk4 = g_packed[pair];           // one LDG.128: 16 indices *4
            unsigned pk[4] = { pk4.x, pk4.y, pk4.z, pk4.w };
            int sp = __ldg(spatial_pos + pair);
            float rden = 1.0f / fmaxf((float)sp, 1.0f);

            float acc[8];
#pragma unroll
            for (int j = 0; j < 8; ++j) acc[j] = 0.0f;

#pragma unroll
            for (int g = 0; g < 4; ++g) {         // d-group of 4: d = 4g..4g+3
                const char* base = (const char*)(shT + ((4 * g) * 16 + kq * 4) * 32);
                unsigned o0 =  pk[g]        & 0xFCu;
                unsigned o1 = (pk[g] >> 8)  & 0xFCu;
                unsigned o2 = (pk[g] >> 16) & 0xFCu;
                unsigned o3 = (pk[g] >> 24);
                const __half2* p0 = (const __half2*)(base          + o0);
                const __half2* p1 = (const __half2*)(base + 2048   + o1);
                const __half2* p2 = (const __half2*)(base + 4096   + o2);
                const __half2* p3 = (const __half2*)(base + 6144   + o3);
#pragma unroll
                for (int j = 0; j < 4; ++j) {     // 4 k2 slots in this quarter
                    __half2 tt = __hadd2(__hadd2(p0[j * 32], p1[j * 32]),
                                         __hadd2(p2[j * 32], p3[j * 32]));
                    float2 f = __half22float2(tt);
                    acc[2 * j]     = fmaf(f.x, rden, acc[2 * j]);
                    acc[2 * j + 1] = fmaf(f.y, rden, acc[2 * j + 1]);
                }
            }

            float* oe = out + (H + kq * 8) * PAIRS + pair;
#pragma unroll
            for (int j = 0; j < 8; ++j)
                oe[j * PAIRS] = acc[j];
        } else {
            // ---------------- phi_spd task: 512 pairs, all 32 heads ------
            int u  = task - N_EDGE_TASKS;         // 0..511
            int pA = u * 512 + t * 2;
            int2 s = ((const int2*)spatial_pos)[pA >> 1];
#pragma unroll
            for (int k2 = 0; k2 < 16; ++k2) {
                float2 fa = __half22float2(shS[k2 * NSPAT + s.x]);
                float2 fb = __half22float2(shS[k2 * NSPAT + s.y]);
                *(float2*)(out + (2 * k2) * PAIRS + pA)     = make_float2(fa.x, fb.x);
                *(float2*)(out + (2 * k2 + 1) * PAIRS + pA) = make_float2(fa.y, fb.y);
            }
        }

        __syncthreads();       // publishes mail[slot]
        task = mail[slot];
        slot ^= 1;
    }
}

extern "C" void kernel_launch(void* const* d_in, const int* in_sizes, int n_in,
                              void* d_out, int out_size) {
    const int*   spatial_pos = nullptr;
    const int*   edge_input  = nullptr;
    const float* spd_table   = nullptr;
    const float* edge_table  = nullptr;
    const float* W           = nullptr;
    for (int i = 0; i < n_in; ++i) {
        switch (in_sizes[i]) {
            case PAIRS:          spatial_pos = (const int*)d_in[i];   break;
            case PAIRS * MAXD:   edge_input  = (const int*)d_in[i];   break;
            case NSPAT * H:      spd_table   = (const float*)d_in[i]; break;
            case H * H:          edge_table  = (const float*)d_in[i]; break;
            case NSPAT * H * H:  W           = (const float*)d_in[i]; break;
            default: break;
        }
    }

    prep_kernel<<<MAXD + PAIRS / 512, 256>>>(edge_table, W, edge_input);

    cudaFuncSetAttribute(bond_encoding_kernel,
                         cudaFuncAttributeMaxDynamicSharedMemorySize, SMEM_BYTES);
    bond_encoding_kernel<<<GRID, 256, SMEM_BYTES>>>(spatial_pos, spd_table,
                                                    (float*)d_out);
}

// round 15
// speedup vs baseline: 1.2000x; 1.2000x over previous
#include <cuda_runtime.h>
#include <cuda_fp16.h>

// ---------------------------------------------------------------------------
// N=512, MAX_DIST=16, H=32, N_SPATIAL=64, BOND_TYPES=32.
// edge_sum[i,j,k] = sum_d T[d][edge_input[i,j,d]][k],  T[d] = edge_table @ W[d]
// R15: prep kernel = ONE launch, 1552 blocks:
//   blocks 0..15     : T[d] precompute (validated)
//   blocks 16..527   : index pack, 2 pairs/thread (validated)
//   blocks 528..1551 : phi_spd, 1 pair/thread, padded-transpose smem gather
//                      (bank=(k+sp)%32, ~2.7 phases) + coalesced STG.32 —
//                      replaces the latency-starved R12 version (10.7us@8%issue)
// Main kernel: R12 phi_edge loop verbatim (16.4us validated).
// ---------------------------------------------------------------------------

#define NN        512
#define PAIRS     (NN * NN)          // 262144
#define MAXD      16
#define H         32
#define NSPAT     64
#define T2_ELEMS  (MAXD * 16 * 32)   // 8192 half2 = 32KB
#define SMEM_BYTES (T2_ELEMS * 4)    // 32768 (main kernel: shT only)
#define GRID      888               // 6 blocks/SM * 148 SMs
#define N_TASKS   4096              // 1024 tiles(256 pairs) * 4 k-quarters

#define PACK_BLOCKS 512             // 2 pairs/thread
#define SPD_BLOCKS  1024            // 256 pairs/block, 1 pair/thread
#define PREP_GRID   (MAXD + PACK_BLOCKS + SPD_BLOCKS)   // 1552

__device__ __half2   g_T2[T2_ELEMS];   // [d][k2][e]
__device__ uint4     g_packed[PAIRS];  // 16 indices, pre-scaled x4, one byte each
__device__ unsigned  g_task_counter;

__global__ __launch_bounds__(256)
void prep_kernel(const float* __restrict__ edge_table,
                 const float* __restrict__ W,
                 const int* __restrict__ edge_input,
                 const int* __restrict__ spatial_pos,
                 const float* __restrict__ spd_table,
                 float* __restrict__ out) {
    __shared__ float shBuf[H * 65 + 64];   // 8.4KB, covers all roles
    int t = threadIdx.x;

    if (blockIdx.x < MAXD) {
        // ---- T[d] = edge_table @ W[d] -> g_T2 (half2 over k) ----
        float* shE = shBuf;            // [h][e]
        float* shW = shBuf + H * H;    // won't fit: reuse layout below
        // NOTE: need 2048 floats; shBuf holds 2144 -> OK.
        int d = blockIdx.x;
        for (int i = t; i < H * H; i += 256) {
            int e = i >> 5, h = i & 31;
            shE[h * H + e] = edge_table[i];
            shW[i] = W[d * (H * H) + i];
        }
        __syncthreads();
        int e = t & 31;
#pragma unroll
        for (int rep = 0; rep < 2; ++rep) {
            int k2 = (t >> 5) + 8 * rep;
            float s0 = 0.0f, s1 = 0.0f;
#pragma unroll
            for (int h = 0; h < H; ++h) {
                float ev = shE[h * H + e];          // bank = e, conflict-free
                s0 += ev * shW[h * H + 2 * k2];     // broadcast
                s1 += ev * shW[h * H + 2 * k2 + 1];
            }
            g_T2[d * 512 + k2 * 32 + e] = __floats2half2_rn(s0, s1);
        }
        return;
    }

    if (blockIdx.x < MAXD + PACK_BLOCKS) {
        // ---- index pack: 2 pairs/thread ----
        if (blockIdx.x == MAXD && t == 0) g_task_counter = 0u;
        int pA = ((blockIdx.x - MAXD) * 256 + t) * 2;
#pragma unroll
        for (int pp = 0; pp < 2; ++pp) {
            int pair = pA + pp;
            const int4* ep = (const int4*)edge_input + pair * 4;
            int4 a = ep[0], b = ep[1], c = ep[2], e4 = ep[3];
            uint4 r;
            r.x = ((unsigned)a.x  << 2) | ((unsigned)a.y  << 10) | ((unsigned)a.z  << 18) | ((unsigned)a.w  << 26);
            r.y = ((unsigned)b.x  << 2) | ((unsigned)b.y  << 10) | ((unsigned)b.z  << 18) | ((unsigned)b.w  << 26);
            r.z = ((unsigned)c.x  << 2) | ((unsigned)c.y  << 10) | ((unsigned)c.z  << 18) | ((unsigned)c.w  << 26);
            r.w = ((unsigned)e4.x << 2) | ((unsigned)e4.y << 10) | ((unsigned)e4.z << 18) | ((unsigned)e4.w << 26);
            g_packed[pair] = r;
        }
        return;
    }

    // ---- phi_spd: 1 pair/thread, 256 pairs/block ----
    // Stage spd transposed with pad 65: shSp[k*65 + sp] = spd_table[sp*32 + k]
    // Coalesced read; write index = lane*65 + w -> bank (lane+w)%32 conflict-free.
    float* shSp = shBuf;
    for (int i = t; i < NSPAT * H; i += 256) {
        int sp = i >> 5;          // consecutive i -> sp = warp id (uniform/warp)
        int k  = i & 31;          // = lane
        shSp[k * 65 + sp] = spd_table[i];
    }
    __syncthreads();

    int pair = (blockIdx.x - MAXD - PACK_BLOCKS) * 256 + t;
    int sp = __ldg(spatial_pos + pair);
#pragma unroll
    for (int k = 0; k < H; ++k) {
        // gather bank = (k*65 + sp) % 32 = (k + sp) % 32: random sp -> ~2.7 phases
        out[k * PAIRS + pair] = shSp[k * 65 + sp];
    }
}

// ---------------- main: phi_edge (R12 verbatim) ----------------
__global__ __launch_bounds__(256, 6)
void bond_encoding_kernel(const int* __restrict__ spatial_pos,
                          float* __restrict__ out) {
    extern __shared__ float sh[];
    __half2* shT = (__half2*)sh;              // [d][k2][e], 32KB
    __shared__ int mail[2];
    const int t = threadIdx.x;

    {
        const float4* src = (const float4*)g_T2;
        float4* dst = (float4*)sh;
#pragma unroll
        for (int i = t; i < T2_ELEMS / 4; i += 256)
            dst[i] = src[i];
    }
    if (t == 0) mail[0] = (int)atomicAdd(&g_task_counter, 1u);
    __syncthreads();

    int task = mail[0];
    int slot = 1;
    while (task < N_TASKS) {
        if (t == 0) mail[slot] = (int)atomicAdd(&g_task_counter, 1u);

        int tile = task >> 2;
        int kq   = task & 3;                  // k-quarter: 8 heads
        int pair = tile * 256 + t;

        uint4 pk4 = g_packed[pair];           // one LDG.128: all 16 indices *4
        unsigned pk[4] = { pk4.x, pk4.y, pk4.z, pk4.w };
        int sp = __ldg(spatial_pos + pair);
        float rden = 1.0f / fmaxf((float)sp, 1.0f);

        float acc[8];
#pragma unroll
        for (int j = 0; j < 8; ++j) acc[j] = 0.0f;

#pragma unroll
        for (int g = 0; g < 4; ++g) {         // d-group of 4: d = 4g..4g+3
            const char* base = (const char*)(shT + ((4 * g) * 16 + kq * 4) * 32);
            unsigned o0 =  pk[g]        & 0xFCu;
            unsigned o1 = (pk[g] >> 8)  & 0xFCu;
            unsigned o2 = (pk[g] >> 16) & 0xFCu;
            unsigned o3 = (pk[g] >> 24);
            const __half2* p0 = (const __half2*)(base          + o0);
            const __half2* p1 = (const __half2*)(base + 2048   + o1);
            const __half2* p2 = (const __half2*)(base + 4096   + o2);
            const __half2* p3 = (const __half2*)(base + 6144   + o3);
#pragma unroll
            for (int j = 0; j < 4; ++j) {     // 4 k2 slots in this quarter
                __half2 tt = __hadd2(__hadd2(p0[j * 32], p1[j * 32]),
                                     __hadd2(p2[j * 32], p3[j * 32]));
                float2 f = __half22float2(tt);
                acc[2 * j]     = fmaf(f.x, rden, acc[2 * j]);
                acc[2 * j + 1] = fmaf(f.y, rden, acc[2 * j + 1]);
            }
        }

        float* oe = out + (H + kq * 8) * PAIRS + pair;
#pragma unroll
        for (int j = 0; j < 8; ++j)
            oe[j * PAIRS] = acc[j];

        __syncthreads();       // publishes mail[slot]
        task = mail[slot];
        slot ^= 1;
    }
}

extern "C" void kernel_launch(void* const* d_in, const int* in_sizes, int n_in,
                              void* d_out, int out_size) {
    const int*   spatial_pos = nullptr;
    const int*   edge_input  = nullptr;
    const float* spd_table   = nullptr;
    const float* edge_table  = nullptr;
    const float* W           = nullptr;
    for (int i = 0; i < n_in; ++i) {
        switch (in_sizes[i]) {
            case PAIRS:          spatial_pos = (const int*)d_in[i];   break;
            case PAIRS * MAXD:   edge_input  = (const int*)d_in[i];   break;
            case NSPAT * H:      spd_table   = (const float*)d_in[i]; break;
            case H * H:          edge_table  = (const float*)d_in[i]; break;
            case NSPAT * H * H:  W           = (const float*)d_in[i]; break;
            default: break;
        }
    }

    prep_kernel<<<PREP_GRID, 256>>>(edge_table, W, edge_input,
                                    spatial_pos, spd_table, (float*)d_out);

    cudaFuncSetAttribute(bond_encoding_kernel,
                         cudaFuncAttributeMaxDynamicSharedMemorySize, SMEM_BYTES);
    bond_encoding_kernel<<<GRID, 256, SMEM_BYTES>>>(spatial_pos, (float*)d_out);
}